// round 10
// baseline (speedup 1.0000x reference)
#include <cuda_runtime.h>
#include <cuda_fp16.h>
#include <math.h>
#include <stdint.h>

#define OUT_N  2048
#define IN_K   2048
#define M_ROWS 8192
#define RANK   4

// ---------------- scratch (static device globals; no runtime alloc) --------
__device__ float  g_coef[8];                   // [0..3]=g_r/||A_r||, [4..7]=1/||B_r||
__device__ __half g_W[(size_t)OUT_N * IN_K];   // fp16 effective weight (8 MB)
__device__ __half g_X[(size_t)M_ROWS * IN_K];  // fp16 activations (32 MB)

__device__ __forceinline__ uint32_t h2_bits(__half2 h) {
    union { __half2 h; uint32_t u; } cvt;
    cvt.h = h;
    return cvt.u;
}

// ---------------- Kernel 1: 8 blocks, one norm each -------------------------
__global__ __launch_bounds__(256) void norm_kernel(const float* __restrict__ sA,
                                                   const float* __restrict__ sB,
                                                   const float* __restrict__ mag)
{
    __shared__ float red[8];
    const int r = blockIdx.x;        // 0..7
    const int tid = threadIdx.x, lid = tid & 31, wid = tid >> 5;
    float s = 0.f;
    if (r < 4) {
        for (int o = tid; o < OUT_N; o += 256) { float v = sA[o * RANK + r]; s += v * v; }
    } else {
        const float* row = sB + (size_t)(r - 4) * IN_K;
        for (int i = tid; i < IN_K; i += 256) { float v = row[i]; s += v * v; }
    }
    for (int off = 16; off; off >>= 1) s += __shfl_xor_sync(0xffffffff, s, off);
    if (lid == 0) red[wid] = s;
    __syncthreads();
    if (tid == 0) {
        float t = 0.f;
        for (int w = 0; w < 8; ++w) t += red[w];
        float nrm = fmaxf(sqrtf(t), 1e-6f);
        if (r < 4) {
            float m = mag[r];
            float g = (m > 20.f ? m : log1pf(expf(m))) + 1e-6f;
            g_coef[r] = g / nrm;
        } else {
            g_coef[r] = 1.f / nrm;
        }
    }
}

// ---------------- Kernel 2: W = half(lut[idx] * dot4(|a|c, |b|c)) -----------
__global__ __launch_bounds__(512) void build_w_kernel(const int* __restrict__ indices,
                                                      const float* __restrict__ lut,
                                                      const float* __restrict__ sA,
                                                      const float* __restrict__ sB)
{
    __shared__ float lsh[16];
    __shared__ float ash[RANK];
    const int o = blockIdx.x;
    const int tid = threadIdx.x;
    if (tid < 16) lsh[tid] = lut[tid];
    if (tid < RANK) ash[tid] = fabsf(sA[o * RANK + tid]) * g_coef[tid];
    __syncthreads();

    const float a0 = ash[0], a1 = ash[1], a2 = ash[2], a3 = ash[3];
    const float c0 = g_coef[4], c1 = g_coef[5], c2 = g_coef[6], c3 = g_coef[7];
    const int i0 = tid * 4;
    const int4 idx = *(const int4*)&indices[(size_t)o * IN_K + i0];
    const float4 b0 = *(const float4*)&sB[0 * IN_K + i0];
    const float4 b1 = *(const float4*)&sB[1 * IN_K + i0];
    const float4 b2 = *(const float4*)&sB[2 * IN_K + i0];
    const float4 b3 = *(const float4*)&sB[3 * IN_K + i0];

    const float k0 = a0 * c0, k1 = a1 * c1, k2 = a2 * c2, k3 = a3 * c3;
    __half2 w01 = __floats2half2_rn(
        lsh[idx.x] * (k0 * fabsf(b0.x) + k1 * fabsf(b1.x) + k2 * fabsf(b2.x) + k3 * fabsf(b3.x)),
        lsh[idx.y] * (k0 * fabsf(b0.y) + k1 * fabsf(b1.y) + k2 * fabsf(b2.y) + k3 * fabsf(b3.y)));
    __half2 w23 = __floats2half2_rn(
        lsh[idx.z] * (k0 * fabsf(b0.z) + k1 * fabsf(b1.z) + k2 * fabsf(b2.z) + k3 * fabsf(b3.z)),
        lsh[idx.w] * (k0 * fabsf(b0.w) + k1 * fabsf(b1.w) + k2 * fabsf(b2.w) + k3 * fabsf(b3.w)));
    uint2 packed = make_uint2(h2_bits(w01), h2_bits(w23));
    *(uint2*)&g_W[(size_t)o * IN_K + i0] = packed;
}

// ---------------- Kernel 3: X -> fp16 ---------------------------------------
__global__ __launch_bounds__(256) void round_x_kernel(const float* __restrict__ x)
{
    size_t i = ((size_t)blockIdx.x * 256 + threadIdx.x) * 8;
    float4 v0 = *(const float4*)&x[i];
    float4 v1 = *(const float4*)&x[i + 4];
    uint4 out;
    out.x = h2_bits(__floats2half2_rn(v0.x, v0.y));
    out.y = h2_bits(__floats2half2_rn(v0.z, v0.w));
    out.z = h2_bits(__floats2half2_rn(v1.x, v1.y));
    out.w = h2_bits(__floats2half2_rn(v1.z, v1.w));
    *(uint4*)&g_X[i] = out;
}

// ---------------- Kernel 4: fp16 mma.sync GEMM, 64x64 warp tiles ------------
// CTA 128x128, 128 threads (4 warps of 64x64), BK=64, 3 stages, 2 CTAs/SM.
#define BM 128
#define BN 128
#define BK 64
#define PADH 72                        // halves per smem row (64 + 8 pad = 144B)
#define STG_HALVES ((BM + BN) * PADH)
#define STG_BYTES (STG_HALVES * 2)     // 36,864 B
#define AS_OFF 0
#define BS_OFF (BM * PADH)
#define NKT (IN_K / BK)                // 32
#define NSTG 3
#define DYN_SMEM (NSTG * STG_BYTES)    // 110,592 B per CTA
#define NTHR 128

__device__ __forceinline__ uint32_t smem_u32(const void* p) {
    uint32_t a;
    asm("{ .reg .u64 t; cvta.to.shared.u64 t, %1; cvt.u32.u64 %0, t; }" : "=r"(a) : "l"(p));
    return a;
}
__device__ __forceinline__ void cp16(void* dst, const void* src) {
    uint32_t d;
    asm("{ .reg .u64 t; cvta.to.shared.u64 t, %1; cvt.u32.u64 %0, t; }" : "=r"(d) : "l"(dst));
    asm volatile("cp.async.cg.shared.global [%0], [%1], 16;" :: "r"(d), "l"(src));
}
__device__ __forceinline__ void cp_commit() {
    asm volatile("cp.async.commit_group;" ::: "memory");
}
template<int N>
__device__ __forceinline__ void cp_wait() {
    asm volatile("cp.async.wait_group %0;" :: "n"(N) : "memory");
}
__device__ __forceinline__ void ldsm_x4(uint32_t* r, uint32_t addr) {
    asm volatile("ldmatrix.sync.aligned.m8n8.x4.shared.b16 {%0,%1,%2,%3}, [%4];"
                 : "=r"(r[0]), "=r"(r[1]), "=r"(r[2]), "=r"(r[3]) : "r"(addr));
}
__device__ __forceinline__ void mma16(float& c0, float& c1, float& c2, float& c3,
                                      uint32_t a0, uint32_t a1, uint32_t a2, uint32_t a3,
                                      uint32_t b0, uint32_t b1) {
    asm volatile(
        "mma.sync.aligned.m16n8k16.row.col.f32.f16.f16.f32 "
        "{%0,%1,%2,%3}, {%4,%5,%6,%7}, {%8,%9}, {%0,%1,%2,%3};"
        : "+f"(c0), "+f"(c1), "+f"(c2), "+f"(c3)
        : "r"(a0), "r"(a1), "r"(a2), "r"(a3), "r"(b0), "r"(b1));
}

__device__ __forceinline__ void issue_stage(__half* smem, int stage, int kbase,
                                            const __half* Ag, const __half* Bg, int tid)
{
    __half* as = smem + (size_t)stage * STG_HALVES + AS_OFF;
    __half* bs = smem + (size_t)stage * STG_HALVES + BS_OFF;
    // 128 rows x 8 chunks = 1024 chunks each; 8 per thread at 128 threads
#pragma unroll
    for (int i = 0; i < 8; ++i) {
        int c = tid + i * NTHR, row = c >> 3, kc = (c & 7) << 3;
        cp16(as + row * PADH + kc, Ag + (size_t)row * IN_K + kbase + kc);
    }
#pragma unroll
    for (int i = 0; i < 8; ++i) {
        int c = tid + i * NTHR, row = c >> 3, kc = (c & 7) << 3;
        cp16(bs + row * PADH + kc, Bg + (size_t)row * IN_K + kbase + kc);
    }
    cp_commit();
}

__global__ __launch_bounds__(NTHR, 2) void gemm_kernel(const float* __restrict__ bias,
                                                       float* __restrict__ Y)
{
    extern __shared__ __half smem[];
    const uint32_t sbase = smem_u32(smem);
    const int tid = threadIdx.x;
    const int wid = tid >> 5, lane = tid & 31;
    const int warp_m = wid & 1, warp_n = wid >> 1;   // 2 x 2 warps; warp tile 64x64
    const int gid = lane >> 2, tig = lane & 3;
    const int bm = blockIdx.y * BM;
    const int bn = blockIdx.x * BN;

    const __half* Ag = g_X + (size_t)bm * IN_K;
    const __half* Bg = g_W + (size_t)bn * IN_K;

    const int lg = lane >> 3, lr = lane & 7;
    // A x4: g0:(m+0,k+0) g1:(m+8,k+0) g2:(m+0,k+8) g3:(m+8,k+8)
    const uint32_t aLane = (uint32_t)(((warp_m * 64 + (lg & 1) * 8 + lr) * PADH
                                       + (lg >> 1) * 8) * 2);
    // B x4: g0:(n+0,k+0) g1:(n+0,k+8) g2:(n+8,k+0) g3:(n+8,k+8)
    const uint32_t bLane = (uint32_t)(((warp_n * 64 + (lg >> 1) * 8 + lr) * PADH
                                       + (lg & 1) * 8 + BS_OFF) * 2);

    float acc[4][8][4];
#pragma unroll
    for (int i = 0; i < 4; ++i)
#pragma unroll
        for (int j = 0; j < 8; ++j)
#pragma unroll
            for (int q = 0; q < 4; ++q) acc[i][j][q] = 0.f;

    issue_stage(smem, 0, 0 * BK, Ag, Bg, tid);
    issue_stage(smem, 1, 1 * BK, Ag, Bg, tid);

    for (int kt = 0; kt < NKT; ++kt) {
        cp_wait<1>();
        __syncthreads();

        const int ldk = kt + 2;
        if (ldk < NKT)
            issue_stage(smem, ldk % NSTG, ldk * BK, Ag, Bg, tid);

        const uint32_t stq = sbase + (uint32_t)(kt % NSTG) * STG_BYTES;
        const uint32_t aQ = stq + aLane;
        const uint32_t bQ = stq + bLane;

#pragma unroll
        for (int ks = 0; ks < 4; ++ks) {      // 4 x k16 per BK=64
            const uint32_t kOff = (uint32_t)(ks * 32);
            uint32_t a[4][4];
#pragma unroll
            for (int mt = 0; mt < 4; ++mt)
                ldsm_x4(a[mt], aQ + (uint32_t)(mt * 16 * PADH * 2) + kOff);
            uint32_t bb[4][4];   // bb[j] covers n-tiles 2j, 2j+1
#pragma unroll
            for (int j = 0; j < 4; ++j)
                ldsm_x4(bb[j], bQ + (uint32_t)(j * 16 * PADH * 2) + kOff);
#pragma unroll
            for (int mt = 0; mt < 4; ++mt)
#pragma unroll
                for (int nt = 0; nt < 8; ++nt)
                    mma16(acc[mt][nt][0], acc[mt][nt][1], acc[mt][nt][2], acc[mt][nt][3],
                          a[mt][0], a[mt][1], a[mt][2], a[mt][3],
                          bb[nt >> 1][(nt & 1) * 2], bb[nt >> 1][(nt & 1) * 2 + 1]);
        }
    }

    // ---- epilogue: bias + store ----
#pragma unroll
    for (int mt = 0; mt < 4; ++mt) {
        const int row0 = bm + warp_m * 64 + mt * 16 + gid;
#pragma unroll
        for (int nt = 0; nt < 8; ++nt) {
            const int col = bn + warp_n * 64 + nt * 8 + tig * 2;
            const float bx = __ldg(&bias[col]);
            const float by = __ldg(&bias[col + 1]);
            float2 v0 = make_float2(acc[mt][nt][0] + bx, acc[mt][nt][1] + by);
            float2 v1 = make_float2(acc[mt][nt][2] + bx, acc[mt][nt][3] + by);
            *(float2*)&Y[(size_t)row0 * OUT_N + col] = v0;
            *(float2*)&Y[(size_t)(row0 + 8) * OUT_N + col] = v1;
        }
    }
}

// ---------------- launch ----------------------------------------------------
extern "C" void kernel_launch(void* const* d_in, const int* in_sizes, int n_in,
                              void* d_out, int out_size)
{
    const float* x       = (const float*)d_in[0];  // [4, 2048, 2048]
    const int*   indices = (const int*)  d_in[1];  // [2048, 2048]
    const float* lut     = (const float*)d_in[2];  // [16]
    const float* sA      = (const float*)d_in[3];  // [2048, 4]
    const float* sB      = (const float*)d_in[4];  // [4, 2048]
    const float* mag     = (const float*)d_in[5];  // [4]
    const float* bias    = (const float*)d_in[6];  // [2048]
    float* y = (float*)d_out;                      // [4, 2048, 2048]

    cudaFuncSetAttribute(gemm_kernel, cudaFuncAttributeMaxDynamicSharedMemorySize, DYN_SMEM);

    round_x_kernel<<<(M_ROWS * IN_K) / (256 * 8), 256>>>(x);
    norm_kernel<<<8, 256>>>(sA, sB, mag);
    build_w_kernel<<<OUT_N, 512>>>(indices, lut, sA, sB);

    dim3 grid(OUT_N / BN, M_ROWS / BM);  // (16, 64)
    gemm_kernel<<<grid, NTHR, DYN_SMEM>>>(bias, y);
}

// round 11
// speedup vs baseline: 1.0530x; 1.0530x over previous
#include <cuda_runtime.h>
#include <cuda_fp16.h>
#include <math.h>
#include <stdint.h>

#define OUT_N  2048
#define IN_K   2048
#define M_ROWS 8192
#define RANK   4

// ---------------- scratch (static device globals; no runtime alloc) --------
__device__ float  g_coef[8];                   // [0..3]=g_r/||A_r||, [4..7]=1/||B_r||
__device__ __half g_W[(size_t)OUT_N * IN_K];   // fp16 effective weight (8 MB)
__device__ __half g_X[(size_t)M_ROWS * IN_K];  // fp16 activations (32 MB)

__device__ __forceinline__ uint32_t h2_bits(__half2 h) {
    union { __half2 h; uint32_t u; } cvt;
    cvt.h = h;
    return cvt.u;
}

// ---------------- Kernel 1: 8 blocks, one norm each -------------------------
__global__ __launch_bounds__(256) void norm_kernel(const float* __restrict__ sA,
                                                   const float* __restrict__ sB,
                                                   const float* __restrict__ mag)
{
    __shared__ float red[8];
    const int r = blockIdx.x;        // 0..7
    const int tid = threadIdx.x, lid = tid & 31, wid = tid >> 5;
    float s = 0.f;
    if (r < 4) {
        for (int o = tid; o < OUT_N; o += 256) { float v = sA[o * RANK + r]; s += v * v; }
    } else {
        const float* row = sB + (size_t)(r - 4) * IN_K;
        for (int i = tid; i < IN_K; i += 256) { float v = row[i]; s += v * v; }
    }
    for (int off = 16; off; off >>= 1) s += __shfl_xor_sync(0xffffffff, s, off);
    if (lid == 0) red[wid] = s;
    __syncthreads();
    if (tid == 0) {
        float t = 0.f;
        for (int w = 0; w < 8; ++w) t += red[w];
        float nrm = fmaxf(sqrtf(t), 1e-6f);
        if (r < 4) {
            float m = mag[r];
            float g = (m > 20.f ? m : log1pf(expf(m))) + 1e-6f;
            g_coef[r] = g / nrm;
        } else {
            g_coef[r] = 1.f / nrm;
        }
    }
}

// ---------------- Kernel 2: W = half(lut[idx] * dot4(|a|c, |b|c)) -----------
__global__ __launch_bounds__(512) void build_w_kernel(const int* __restrict__ indices,
                                                      const float* __restrict__ lut,
                                                      const float* __restrict__ sA,
                                                      const float* __restrict__ sB)
{
    __shared__ float lsh[16];
    __shared__ float ash[RANK];
    const int o = blockIdx.x;
    const int tid = threadIdx.x;
    if (tid < 16) lsh[tid] = lut[tid];
    if (tid < RANK) ash[tid] = fabsf(sA[o * RANK + tid]) * g_coef[tid];
    __syncthreads();

    const float a0 = ash[0], a1 = ash[1], a2 = ash[2], a3 = ash[3];
    const float c0 = g_coef[4], c1 = g_coef[5], c2 = g_coef[6], c3 = g_coef[7];
    const int i0 = tid * 4;
    const int4 idx = *(const int4*)&indices[(size_t)o * IN_K + i0];
    const float4 b0 = *(const float4*)&sB[0 * IN_K + i0];
    const float4 b1 = *(const float4*)&sB[1 * IN_K + i0];
    const float4 b2 = *(const float4*)&sB[2 * IN_K + i0];
    const float4 b3 = *(const float4*)&sB[3 * IN_K + i0];

    const float k0 = a0 * c0, k1 = a1 * c1, k2 = a2 * c2, k3 = a3 * c3;
    __half2 w01 = __floats2half2_rn(
        lsh[idx.x] * (k0 * fabsf(b0.x) + k1 * fabsf(b1.x) + k2 * fabsf(b2.x) + k3 * fabsf(b3.x)),
        lsh[idx.y] * (k0 * fabsf(b0.y) + k1 * fabsf(b1.y) + k2 * fabsf(b2.y) + k3 * fabsf(b3.y)));
    __half2 w23 = __floats2half2_rn(
        lsh[idx.z] * (k0 * fabsf(b0.z) + k1 * fabsf(b1.z) + k2 * fabsf(b2.z) + k3 * fabsf(b3.z)),
        lsh[idx.w] * (k0 * fabsf(b0.w) + k1 * fabsf(b1.w) + k2 * fabsf(b2.w) + k3 * fabsf(b3.w)));
    uint2 packed = make_uint2(h2_bits(w01), h2_bits(w23));
    *(uint2*)&g_W[(size_t)o * IN_K + i0] = packed;
}

// ---------------- Kernel 3: X -> fp16 ---------------------------------------
__global__ __launch_bounds__(256) void round_x_kernel(const float* __restrict__ x)
{
    size_t i = ((size_t)blockIdx.x * 256 + threadIdx.x) * 8;
    float4 v0 = *(const float4*)&x[i];
    float4 v1 = *(const float4*)&x[i + 4];
    uint4 out;
    out.x = h2_bits(__floats2half2_rn(v0.x, v0.y));
    out.y = h2_bits(__floats2half2_rn(v0.z, v0.w));
    out.z = h2_bits(__floats2half2_rn(v1.x, v1.y));
    out.w = h2_bits(__floats2half2_rn(v1.z, v1.w));
    *(uint4*)&g_X[i] = out;
}

// ---------------- Kernel 4: fp16 mma.sync GEMM + ldmatrix + ks stagger ------
// CTA 128x128, 256 threads (8 warps of 64x32), BK=64, 3 stages, 2 CTAs/SM.
#define BM 128
#define BN 128
#define BK 64
#define PADH 72                        // halves per smem row (64 + 8 pad = 144B)
#define STG_HALVES ((BM + BN) * PADH)
#define STG_BYTES (STG_HALVES * 2)     // 36,864 B
#define AS_OFF 0
#define BS_OFF (BM * PADH)
#define NKT (IN_K / BK)                // 32
#define NSTG 3
#define DYN_SMEM (NSTG * STG_BYTES)    // 110,592 B

__device__ __forceinline__ uint32_t smem_u32(const void* p) {
    uint32_t a;
    asm("{ .reg .u64 t; cvta.to.shared.u64 t, %1; cvt.u32.u64 %0, t; }" : "=r"(a) : "l"(p));
    return a;
}
__device__ __forceinline__ void cp16(void* dst, const void* src) {
    uint32_t d;
    asm("{ .reg .u64 t; cvta.to.shared.u64 t, %1; cvt.u32.u64 %0, t; }" : "=r"(d) : "l"(dst));
    asm volatile("cp.async.cg.shared.global [%0], [%1], 16;" :: "r"(d), "l"(src));
}
__device__ __forceinline__ void cp_commit() {
    asm volatile("cp.async.commit_group;" ::: "memory");
}
template<int N>
__device__ __forceinline__ void cp_wait() {
    asm volatile("cp.async.wait_group %0;" :: "n"(N) : "memory");
}
__device__ __forceinline__ void ldsm_x4(uint32_t* r, uint32_t addr) {
    asm volatile("ldmatrix.sync.aligned.m8n8.x4.shared.b16 {%0,%1,%2,%3}, [%4];"
                 : "=r"(r[0]), "=r"(r[1]), "=r"(r[2]), "=r"(r[3]) : "r"(addr));
}
__device__ __forceinline__ void mma16(float& c0, float& c1, float& c2, float& c3,
                                      uint32_t a0, uint32_t a1, uint32_t a2, uint32_t a3,
                                      uint32_t b0, uint32_t b1) {
    asm volatile(
        "mma.sync.aligned.m16n8k16.row.col.f32.f16.f16.f32 "
        "{%0,%1,%2,%3}, {%4,%5,%6,%7}, {%8,%9}, {%0,%1,%2,%3};"
        : "+f"(c0), "+f"(c1), "+f"(c2), "+f"(c3)
        : "r"(a0), "r"(a1), "r"(a2), "r"(a3), "r"(b0), "r"(b1));
}

__device__ __forceinline__ void issue_stage(__half* smem, int stage, int kbase,
                                            const __half* Ag, const __half* Bg, int tid)
{
    __half* as = smem + (size_t)stage * STG_HALVES + AS_OFF;
    __half* bs = smem + (size_t)stage * STG_HALVES + BS_OFF;
#pragma unroll
    for (int i = 0; i < 4; ++i) {
        int c = tid + i * 256, row = c >> 3, kc = (c & 7) << 3;
        cp16(as + row * PADH + kc, Ag + (size_t)row * IN_K + kbase + kc);
    }
#pragma unroll
    for (int i = 0; i < 4; ++i) {
        int c = tid + i * 256, row = c >> 3, kc = (c & 7) << 3;
        cp16(bs + row * PADH + kc, Bg + (size_t)row * IN_K + kbase + kc);
    }
    cp_commit();
}

__global__ __launch_bounds__(256, 2) void gemm_kernel(const float* __restrict__ bias,
                                                      float* __restrict__ Y)
{
    extern __shared__ __half smem[];
    const uint32_t sbase = smem_u32(smem);
    const int tid = threadIdx.x;
    const int wid = tid >> 5, lane = tid & 31;
    const int warp_m = wid & 1, warp_n = wid >> 1;   // 2 x 4 warps; warp tile 64x32
    const int gid = lane >> 2, tig = lane & 3;
    const int bm = blockIdx.y * BM;
    const int bn = blockIdx.x * BN;
    const int ks0 = wid & 3;                         // per-warp phase stagger

    const __half* Ag = g_X + (size_t)bm * IN_K;
    const __half* Bg = g_W + (size_t)bn * IN_K;

    const int lg = lane >> 3, lr = lane & 7;
    // A x4: g0:(m+0,k+0) g1:(m+8,k+0) g2:(m+0,k+8) g3:(m+8,k+8)
    const uint32_t aLane = (uint32_t)(((warp_m * 64 + (lg & 1) * 8 + lr) * PADH
                                       + (lg >> 1) * 8) * 2);
    // B x4: g0:(n+0,k+0) g1:(n+0,k+8) g2:(n+8,k+0) g3:(n+8,k+8)
    const uint32_t bLane = (uint32_t)(((warp_n * 32 + (lg >> 1) * 8 + lr) * PADH
                                       + (lg & 1) * 8 + BS_OFF) * 2);

    float acc[4][4][4];
#pragma unroll
    for (int i = 0; i < 4; ++i)
#pragma unroll
        for (int j = 0; j < 4; ++j)
#pragma unroll
            for (int q = 0; q < 4; ++q) acc[i][j][q] = 0.f;

    issue_stage(smem, 0, 0 * BK, Ag, Bg, tid);
    issue_stage(smem, 1, 1 * BK, Ag, Bg, tid);

    for (int kt = 0; kt < NKT; ++kt) {
        cp_wait<1>();
        __syncthreads();

        const int ldk = kt + 2;
        if (ldk < NKT)
            issue_stage(smem, ldk % NSTG, ldk * BK, Ag, Bg, tid);

        const uint32_t stq = sbase + (uint32_t)(kt % NSTG) * STG_BYTES;
        const uint32_t aQ = stq + aLane;
        const uint32_t bQ = stq + bLane;

#pragma unroll
        for (int i = 0; i < 4; ++i) {         // 4 x k16, staggered start per warp
            const int ks = (ks0 + i) & 3;
            const uint32_t kOff = (uint32_t)(ks * 32);
            uint32_t a[4][4];
#pragma unroll
            for (int mt = 0; mt < 4; ++mt)
                ldsm_x4(a[mt], aQ + (uint32_t)(mt * 16 * PADH * 2) + kOff);
            uint32_t bb[2][4];
#pragma unroll
            for (int j = 0; j < 2; ++j)
                ldsm_x4(bb[j], bQ + (uint32_t)(j * 16 * PADH * 2) + kOff);
#pragma unroll
            for (int mt = 0; mt < 4; ++mt)
#pragma unroll
                for (int nt = 0; nt < 4; ++nt)
                    mma16(acc[mt][nt][0], acc[mt][nt][1], acc[mt][nt][2], acc[mt][nt][3],
                          a[mt][0], a[mt][1], a[mt][2], a[mt][3],
                          bb[nt >> 1][(nt & 1) * 2], bb[nt >> 1][(nt & 1) * 2 + 1]);
        }
    }

    // ---- epilogue: bias + store ----
#pragma unroll
    for (int mt = 0; mt < 4; ++mt) {
        const int row0 = bm + warp_m * 64 + mt * 16 + gid;
#pragma unroll
        for (int nt = 0; nt < 4; ++nt) {
            const int col = bn + warp_n * 32 + nt * 8 + tig * 2;
            const float bx = __ldg(&bias[col]);
            const float by = __ldg(&bias[col + 1]);
            float2 v0 = make_float2(acc[mt][nt][0] + bx, acc[mt][nt][1] + by);
            float2 v1 = make_float2(acc[mt][nt][2] + bx, acc[mt][nt][3] + by);
            *(float2*)&Y[(size_t)row0 * OUT_N + col] = v0;
            *(float2*)&Y[(size_t)(row0 + 8) * OUT_N + col] = v1;
        }
    }
}

// ---------------- launch ----------------------------------------------------
extern "C" void kernel_launch(void* const* d_in, const int* in_sizes, int n_in,
                              void* d_out, int out_size)
{
    const float* x       = (const float*)d_in[0];  // [4, 2048, 2048]
    const int*   indices = (const int*)  d_in[1];  // [2048, 2048]
    const float* lut     = (const float*)d_in[2];  // [16]
    const float* sA      = (const float*)d_in[3];  // [2048, 4]
    const float* sB      = (const float*)d_in[4];  // [4, 2048]
    const float* mag     = (const float*)d_in[5];  // [4]
    const float* bias    = (const float*)d_in[6];  // [2048]
    float* y = (float*)d_out;                      // [4, 2048, 2048]

    cudaFuncSetAttribute(gemm_kernel, cudaFuncAttributeMaxDynamicSharedMemorySize, DYN_SMEM);

    round_x_kernel<<<(M_ROWS * IN_K) / (256 * 8), 256>>>(x);
    norm_kernel<<<8, 256>>>(sA, sB, mag);
    build_w_kernel<<<OUT_N, 512>>>(indices, lut, sA, sB);

    dim3 grid(OUT_N / BN, M_ROWS / BM);  // (16, 64)
    gemm_kernel<<<grid, 256, DYN_SMEM>>>(bias, y);
}

// round 12
// speedup vs baseline: 1.0934x; 1.0384x over previous
#include <cuda_runtime.h>
#include <cuda_fp16.h>
#include <math.h>
#include <stdint.h>

#define OUT_N  2048
#define IN_K   2048
#define M_ROWS 8192
#define RANK   4

// ---------------- scratch (static device globals; no runtime alloc) --------
__device__ float  g_coef[8];                   // [0..3]=g_r/||A_r||, [4..7]=1/||B_r||
__device__ __half g_W[(size_t)OUT_N * IN_K];   // fp16 effective weight (8 MB)
__device__ __half g_X[(size_t)M_ROWS * IN_K];  // fp16 activations (32 MB)

__device__ __forceinline__ uint32_t h2_bits(__half2 h) {
    union { __half2 h; uint32_t u; } cvt;
    cvt.h = h;
    return cvt.u;
}

// ---------------- Kernel 1: 8 blocks, one norm each -------------------------
__global__ __launch_bounds__(256) void norm_kernel(const float* __restrict__ sA,
                                                   const float* __restrict__ sB,
                                                   const float* __restrict__ mag)
{
    __shared__ float red[8];
    const int r = blockIdx.x;        // 0..7
    const int tid = threadIdx.x, lid = tid & 31, wid = tid >> 5;
    float s = 0.f;
    if (r < 4) {
        for (int o = tid; o < OUT_N; o += 256) { float v = sA[o * RANK + r]; s += v * v; }
    } else {
        const float* row = sB + (size_t)(r - 4) * IN_K;
        for (int i = tid; i < IN_K; i += 256) { float v = row[i]; s += v * v; }
    }
    for (int off = 16; off; off >>= 1) s += __shfl_xor_sync(0xffffffff, s, off);
    if (lid == 0) red[wid] = s;
    __syncthreads();
    if (tid == 0) {
        float t = 0.f;
        for (int w = 0; w < 8; ++w) t += red[w];
        float nrm = fmaxf(sqrtf(t), 1e-6f);
        if (r < 4) {
            float m = mag[r];
            float g = (m > 20.f ? m : log1pf(expf(m))) + 1e-6f;
            g_coef[r] = g / nrm;
        } else {
            g_coef[r] = 1.f / nrm;
        }
    }
}

// ---------------- Kernel 2: W = half(lut[idx] * dot4(|a|c, |b|c)) -----------
__global__ __launch_bounds__(512) void build_w_kernel(const int* __restrict__ indices,
                                                      const float* __restrict__ lut,
                                                      const float* __restrict__ sA,
                                                      const float* __restrict__ sB)
{
    __shared__ float lsh[16];
    __shared__ float ash[RANK];
    const int o = blockIdx.x;
    const int tid = threadIdx.x;
    if (tid < 16) lsh[tid] = lut[tid];
    if (tid < RANK) ash[tid] = fabsf(sA[o * RANK + tid]) * g_coef[tid];
    __syncthreads();

    const float a0 = ash[0], a1 = ash[1], a2 = ash[2], a3 = ash[3];
    const float c0 = g_coef[4], c1 = g_coef[5], c2 = g_coef[6], c3 = g_coef[7];
    const int i0 = tid * 4;
    const int4 idx = *(const int4*)&indices[(size_t)o * IN_K + i0];
    const float4 b0 = *(const float4*)&sB[0 * IN_K + i0];
    const float4 b1 = *(const float4*)&sB[1 * IN_K + i0];
    const float4 b2 = *(const float4*)&sB[2 * IN_K + i0];
    const float4 b3 = *(const float4*)&sB[3 * IN_K + i0];

    const float k0 = a0 * c0, k1 = a1 * c1, k2 = a2 * c2, k3 = a3 * c3;
    __half2 w01 = __floats2half2_rn(
        lsh[idx.x] * (k0 * fabsf(b0.x) + k1 * fabsf(b1.x) + k2 * fabsf(b2.x) + k3 * fabsf(b3.x)),
        lsh[idx.y] * (k0 * fabsf(b0.y) + k1 * fabsf(b1.y) + k2 * fabsf(b2.y) + k3 * fabsf(b3.y)));
    __half2 w23 = __floats2half2_rn(
        lsh[idx.z] * (k0 * fabsf(b0.z) + k1 * fabsf(b1.z) + k2 * fabsf(b2.z) + k3 * fabsf(b3.z)),
        lsh[idx.w] * (k0 * fabsf(b0.w) + k1 * fabsf(b1.w) + k2 * fabsf(b2.w) + k3 * fabsf(b3.w)));
    uint2 packed = make_uint2(h2_bits(w01), h2_bits(w23));
    *(uint2*)&g_W[(size_t)o * IN_K + i0] = packed;
}

// ---------------- Kernel 3: X -> fp16 ---------------------------------------
__global__ __launch_bounds__(256) void round_x_kernel(const float* __restrict__ x)
{
    size_t i = ((size_t)blockIdx.x * 256 + threadIdx.x) * 8;
    float4 v0 = *(const float4*)&x[i];
    float4 v1 = *(const float4*)&x[i + 4];
    uint4 out;
    out.x = h2_bits(__floats2half2_rn(v0.x, v0.y));
    out.y = h2_bits(__floats2half2_rn(v0.z, v0.w));
    out.z = h2_bits(__floats2half2_rn(v1.x, v1.y));
    out.w = h2_bits(__floats2half2_rn(v1.z, v1.w));
    *(uint4*)&g_X[i] = out;
}

// ---------------- Kernel 4: fp16 mma.sync GEMM, 64x64 warp tiles, 3 CTA/SM --
// CTA 128x128, 128 threads (4 warps of 64x64), BK=64, 2 stages, 3 CTAs/SM.
#define BM 128
#define BN 128
#define BK 64
#define PADH 72                        // halves per smem row (64 + 8 pad = 144B)
#define STG_HALVES ((BM + BN) * PADH)
#define STG_BYTES (STG_HALVES * 2)     // 36,864 B
#define AS_OFF 0
#define BS_OFF (BM * PADH)
#define NKT (IN_K / BK)                // 32
#define NSTG 2
#define DYN_SMEM (NSTG * STG_BYTES)    // 73,728 B per CTA
#define NTHR 128

__device__ __forceinline__ uint32_t smem_u32(const void* p) {
    uint32_t a;
    asm("{ .reg .u64 t; cvta.to.shared.u64 t, %1; cvt.u32.u64 %0, t; }" : "=r"(a) : "l"(p));
    return a;
}
__device__ __forceinline__ void cp16(void* dst, const void* src) {
    uint32_t d;
    asm("{ .reg .u64 t; cvta.to.shared.u64 t, %1; cvt.u32.u64 %0, t; }" : "=r"(d) : "l"(dst));
    asm volatile("cp.async.cg.shared.global [%0], [%1], 16;" :: "r"(d), "l"(src));
}
__device__ __forceinline__ void cp_commit() {
    asm volatile("cp.async.commit_group;" ::: "memory");
}
template<int N>
__device__ __forceinline__ void cp_wait() {
    asm volatile("cp.async.wait_group %0;" :: "n"(N) : "memory");
}
__device__ __forceinline__ void ldsm_x4(uint32_t* r, uint32_t addr) {
    asm volatile("ldmatrix.sync.aligned.m8n8.x4.shared.b16 {%0,%1,%2,%3}, [%4];"
                 : "=r"(r[0]), "=r"(r[1]), "=r"(r[2]), "=r"(r[3]) : "r"(addr));
}
__device__ __forceinline__ void mma16(float& c0, float& c1, float& c2, float& c3,
                                      uint32_t a0, uint32_t a1, uint32_t a2, uint32_t a3,
                                      uint32_t b0, uint32_t b1) {
    asm volatile(
        "mma.sync.aligned.m16n8k16.row.col.f32.f16.f16.f32 "
        "{%0,%1,%2,%3}, {%4,%5,%6,%7}, {%8,%9}, {%0,%1,%2,%3};"
        : "+f"(c0), "+f"(c1), "+f"(c2), "+f"(c3)
        : "r"(a0), "r"(a1), "r"(a2), "r"(a3), "r"(b0), "r"(b1));
}

__device__ __forceinline__ void issue_stage(__half* smem, int stage, int kbase,
                                            const __half* Ag, const __half* Bg, int tid)
{
    __half* as = smem + (size_t)stage * STG_HALVES + AS_OFF;
    __half* bs = smem + (size_t)stage * STG_HALVES + BS_OFF;
    // 128 rows x 8 chunks = 1024 chunks each; 8 per thread at 128 threads
#pragma unroll
    for (int i = 0; i < 8; ++i) {
        int c = tid + i * NTHR, row = c >> 3, kc = (c & 7) << 3;
        cp16(as + row * PADH + kc, Ag + (size_t)row * IN_K + kbase + kc);
    }
#pragma unroll
    for (int i = 0; i < 8; ++i) {
        int c = tid + i * NTHR, row = c >> 3, kc = (c & 7) << 3;
        cp16(bs + row * PADH + kc, Bg + (size_t)row * IN_K + kbase + kc);
    }
    cp_commit();
}

__global__ __launch_bounds__(NTHR, 3) void gemm_kernel(const float* __restrict__ bias,
                                                       float* __restrict__ Y)
{
    extern __shared__ __half smem[];
    const uint32_t sbase = smem_u32(smem);
    const int tid = threadIdx.x;
    const int wid = tid >> 5, lane = tid & 31;
    const int warp_m = wid & 1, warp_n = wid >> 1;   // 2 x 2 warps; warp tile 64x64
    const int gid = lane >> 2, tig = lane & 3;
    const int bm = blockIdx.y * BM;
    const int bn = blockIdx.x * BN;

    const __half* Ag = g_X + (size_t)bm * IN_K;
    const __half* Bg = g_W + (size_t)bn * IN_K;

    const int lg = lane >> 3, lr = lane & 7;
    const uint32_t aLane = (uint32_t)(((warp_m * 64 + (lg & 1) * 8 + lr) * PADH
                                       + (lg >> 1) * 8) * 2);
    const uint32_t bLane = (uint32_t)(((warp_n * 64 + (lg >> 1) * 8 + lr) * PADH
                                       + (lg & 1) * 8 + BS_OFF) * 2);

    float acc[4][8][4];
#pragma unroll
    for (int i = 0; i < 4; ++i)
#pragma unroll
        for (int j = 0; j < 8; ++j)
#pragma unroll
            for (int q = 0; q < 4; ++q) acc[i][j][q] = 0.f;

    // ---- prologue: stage 0 ----
    issue_stage(smem, 0, 0, Ag, Bg, tid);

    for (int kt = 0; kt < NKT; ++kt) {
        // buffer (kt+1)%2 was fully consumed in iter kt-1 (or never used yet)
        __syncthreads();
        const int ldk = kt + 1;
        if (ldk < NKT)
            issue_stage(smem, ldk & 1, ldk * BK, Ag, Bg, tid);
        cp_wait<1>();          // stage kt resident (only ldk group outstanding)
        // no extra barrier needed: every thread observes its own wait; data
        // visibility across threads is guaranteed by the barrier at loop top
        // of the NEXT iteration... but compute reads OTHER threads' cp data,
        // so we do need a barrier after wait:
        __syncthreads();

        const uint32_t stq = sbase + (uint32_t)(kt & 1) * STG_BYTES;
        const uint32_t aQ = stq + aLane;
        const uint32_t bQ = stq + bLane;

#pragma unroll
        for (int ks = 0; ks < 4; ++ks) {
            const uint32_t kOff = (uint32_t)(ks * 32);
            uint32_t a[4][4];
#pragma unroll
            for (int mt = 0; mt < 4; ++mt)
                ldsm_x4(a[mt], aQ + (uint32_t)(mt * 16 * PADH * 2) + kOff);
            uint32_t bb[4][4];
#pragma unroll
            for (int j = 0; j < 4; ++j)
                ldsm_x4(bb[j], bQ + (uint32_t)(j * 16 * PADH * 2) + kOff);
#pragma unroll
            for (int mt = 0; mt < 4; ++mt)
#pragma unroll
                for (int nt = 0; nt < 8; ++nt)
                    mma16(acc[mt][nt][0], acc[mt][nt][1], acc[mt][nt][2], acc[mt][nt][3],
                          a[mt][0], a[mt][1], a[mt][2], a[mt][3],
                          bb[nt >> 1][(nt & 1) * 2], bb[nt >> 1][(nt & 1) * 2 + 1]);
        }
    }

    // ---- epilogue: bias + store ----
#pragma unroll
    for (int mt = 0; mt < 4; ++mt) {
        const int row0 = bm + warp_m * 64 + mt * 16 + gid;
#pragma unroll
        for (int nt = 0; nt < 8; ++nt) {
            const int col = bn + warp_n * 64 + nt * 8 + tig * 2;
            const float bx = __ldg(&bias[col]);
            const float by = __ldg(&bias[col + 1]);
            float2 v0 = make_float2(acc[mt][nt][0] + bx, acc[mt][nt][1] + by);
            float2 v1 = make_float2(acc[mt][nt][2] + bx, acc[mt][nt][3] + by);
            *(float2*)&Y[(size_t)row0 * OUT_N + col] = v0;
            *(float2*)&Y[(size_t)(row0 + 8) * OUT_N + col] = v1;
        }
    }
}

// ---------------- launch ----------------------------------------------------
extern "C" void kernel_launch(void* const* d_in, const int* in_sizes, int n_in,
                              void* d_out, int out_size)
{
    const float* x       = (const float*)d_in[0];  // [4, 2048, 2048]
    const int*   indices = (const int*)  d_in[1];  // [2048, 2048]
    const float* lut     = (const float*)d_in[2];  // [16]
    const float* sA      = (const float*)d_in[3];  // [2048, 4]
    const float* sB      = (const float*)d_in[4];  // [4, 2048]
    const float* mag     = (const float*)d_in[5];  // [4]
    const float* bias    = (const float*)d_in[6];  // [2048]
    float* y = (float*)d_out;                      // [4, 2048, 2048]

    cudaFuncSetAttribute(gemm_kernel, cudaFuncAttributeMaxDynamicSharedMemorySize, DYN_SMEM);

    round_x_kernel<<<(M_ROWS * IN_K) / (256 * 8), 256>>>(x);
    norm_kernel<<<8, 256>>>(sA, sB, mag);
    build_w_kernel<<<OUT_N, 512>>>(indices, lut, sA, sB);

    dim3 grid(OUT_N / BN, M_ROWS / BM);  // (16, 64)
    gemm_kernel<<<grid, NTHR, DYN_SMEM>>>(bias, y);
}

// round 13
// speedup vs baseline: 1.0939x; 1.0004x over previous
#include <cuda_runtime.h>
#include <cuda_fp16.h>
#include <math.h>
#include <stdint.h>

#define OUT_N  2048
#define IN_K   2048
#define M_ROWS 8192
#define RANK   4

// ---------------- scratch (static device globals; no runtime alloc) --------
__device__ float  g_coef[8];                   // [0..3]=g_r/||A_r||, [4..7]=1/||B_r||
__device__ __half g_W[(size_t)OUT_N * IN_K];   // fp16 effective weight (8 MB)
__device__ __half g_X[(size_t)M_ROWS * IN_K];  // fp16 activations (32 MB)

__device__ __forceinline__ uint32_t h2_bits(__half2 h) {
    union { __half2 h; uint32_t u; } cvt;
    cvt.h = h;
    return cvt.u;
}

// ---------------- Kernel 1: 8 blocks, one norm each -------------------------
__global__ __launch_bounds__(256) void norm_kernel(const float* __restrict__ sA,
                                                   const float* __restrict__ sB,
                                                   const float* __restrict__ mag)
{
    __shared__ float red[8];
    const int r = blockIdx.x;        // 0..7
    const int tid = threadIdx.x, lid = tid & 31, wid = tid >> 5;
    float s = 0.f;
    if (r < 4) {
        for (int o = tid; o < OUT_N; o += 256) { float v = sA[o * RANK + r]; s += v * v; }
    } else {
        const float* row = sB + (size_t)(r - 4) * IN_K;
        for (int i = tid; i < IN_K; i += 256) { float v = row[i]; s += v * v; }
    }
    for (int off = 16; off; off >>= 1) s += __shfl_xor_sync(0xffffffff, s, off);
    if (lid == 0) red[wid] = s;
    __syncthreads();
    if (tid == 0) {
        float t = 0.f;
        for (int w = 0; w < 8; ++w) t += red[w];
        float nrm = fmaxf(sqrtf(t), 1e-6f);
        if (r < 4) {
            float m = mag[r];
            float g = (m > 20.f ? m : log1pf(expf(m))) + 1e-6f;
            g_coef[r] = g / nrm;
        } else {
            g_coef[r] = 1.f / nrm;
        }
    }
}

// ---------------- Kernel 2 (fused): build W  +  convert X -------------------
// blocks [0, 2048): W row o = blockIdx.x, 256 thr x 8 cols
// blocks [2048, 2048+8192): X fp32->fp16, 256 thr x 8 elems
#define XBLOCKS ((M_ROWS * IN_K) / (256 * 8))   // 8192

__global__ __launch_bounds__(256) void prep_fused_kernel(const int* __restrict__ indices,
                                                         const float* __restrict__ lut,
                                                         const float* __restrict__ sA,
                                                         const float* __restrict__ sB,
                                                         const float* __restrict__ x)
{
    if (blockIdx.x >= OUT_N) {
        // ---- round_x part ----
        size_t i = ((size_t)(blockIdx.x - OUT_N) * 256 + threadIdx.x) * 8;
        float4 v0 = *(const float4*)&x[i];
        float4 v1 = *(const float4*)&x[i + 4];
        uint4 out;
        out.x = h2_bits(__floats2half2_rn(v0.x, v0.y));
        out.y = h2_bits(__floats2half2_rn(v0.z, v0.w));
        out.z = h2_bits(__floats2half2_rn(v1.x, v1.y));
        out.w = h2_bits(__floats2half2_rn(v1.z, v1.w));
        *(uint4*)&g_X[i] = out;
        return;
    }

    // ---- build_w part ----
    __shared__ float lsh[16];
    __shared__ float ash[RANK];
    const int o = blockIdx.x;
    const int tid = threadIdx.x;
    if (tid < 16) lsh[tid] = lut[tid];
    if (tid < RANK) ash[tid] = fabsf(sA[o * RANK + tid]) * g_coef[tid];
    __syncthreads();

    const float k0 = ash[0] * g_coef[4], k1 = ash[1] * g_coef[5];
    const float k2 = ash[2] * g_coef[6], k3 = ash[3] * g_coef[7];

#pragma unroll
    for (int half = 0; half < 2; ++half) {
        const int i0 = tid * 4 + half * 1024;
        const int4 idx = *(const int4*)&indices[(size_t)o * IN_K + i0];
        const float4 b0 = *(const float4*)&sB[0 * IN_K + i0];
        const float4 b1 = *(const float4*)&sB[1 * IN_K + i0];
        const float4 b2 = *(const float4*)&sB[2 * IN_K + i0];
        const float4 b3 = *(const float4*)&sB[3 * IN_K + i0];

        __half2 w01 = __floats2half2_rn(
            lsh[idx.x] * (k0 * fabsf(b0.x) + k1 * fabsf(b1.x) + k2 * fabsf(b2.x) + k3 * fabsf(b3.x)),
            lsh[idx.y] * (k0 * fabsf(b0.y) + k1 * fabsf(b1.y) + k2 * fabsf(b2.y) + k3 * fabsf(b3.y)));
        __half2 w23 = __floats2half2_rn(
            lsh[idx.z] * (k0 * fabsf(b0.z) + k1 * fabsf(b1.z) + k2 * fabsf(b2.z) + k3 * fabsf(b3.z)),
            lsh[idx.w] * (k0 * fabsf(b0.w) + k1 * fabsf(b1.w) + k2 * fabsf(b2.w) + k3 * fabsf(b3.w)));
        uint2 packed = make_uint2(h2_bits(w01), h2_bits(w23));
        *(uint2*)&g_W[(size_t)o * IN_K + i0] = packed;
    }
}

// ---------------- Kernel 3: fp16 mma.sync GEMM (R8 config, race-fixed) ------
// CTA 128x128, 256 threads (8 warps of 64x32), BK=64, 3 stages, 2 CTAs/SM.
#define BM 128
#define BN 128
#define BK 64
#define PADH 72                        // halves per smem row (64 + 8 pad = 144B)
#define STG_HALVES ((BM + BN) * PADH)
#define STG_BYTES (STG_HALVES * 2)     // 36,864 B
#define AS_OFF 0
#define BS_OFF (BM * PADH)
#define NKT (IN_K / BK)                // 32
#define NSTG 3
#define DYN_SMEM (NSTG * STG_BYTES)    // 110,592 B

__device__ __forceinline__ uint32_t smem_u32(const void* p) {
    uint32_t a;
    asm("{ .reg .u64 t; cvta.to.shared.u64 t, %1; cvt.u32.u64 %0, t; }" : "=r"(a) : "l"(p));
    return a;
}
__device__ __forceinline__ void cp16(void* dst, const void* src) {
    uint32_t d;
    asm("{ .reg .u64 t; cvta.to.shared.u64 t, %1; cvt.u32.u64 %0, t; }" : "=r"(d) : "l"(dst));
    asm volatile("cp.async.cg.shared.global [%0], [%1], 16;" :: "r"(d), "l"(src));
}
__device__ __forceinline__ void cp_commit() {
    asm volatile("cp.async.commit_group;" ::: "memory");
}
template<int N>
__device__ __forceinline__ void cp_wait() {
    asm volatile("cp.async.wait_group %0;" :: "n"(N) : "memory");
}
__device__ __forceinline__ void ldsm_x4(uint32_t* r, uint32_t addr) {
    asm volatile("ldmatrix.sync.aligned.m8n8.x4.shared.b16 {%0,%1,%2,%3}, [%4];"
                 : "=r"(r[0]), "=r"(r[1]), "=r"(r[2]), "=r"(r[3]) : "r"(addr));
}
__device__ __forceinline__ void mma16(float& c0, float& c1, float& c2, float& c3,
                                      uint32_t a0, uint32_t a1, uint32_t a2, uint32_t a3,
                                      uint32_t b0, uint32_t b1) {
    asm volatile(
        "mma.sync.aligned.m16n8k16.row.col.f32.f16.f16.f32 "
        "{%0,%1,%2,%3}, {%4,%5,%6,%7}, {%8,%9}, {%0,%1,%2,%3};"
        : "+f"(c0), "+f"(c1), "+f"(c2), "+f"(c3)
        : "r"(a0), "r"(a1), "r"(a2), "r"(a3), "r"(b0), "r"(b1));
}

__device__ __forceinline__ void issue_stage(__half* smem, int stage, int kbase,
                                            const __half* Ag, const __half* Bg, int tid)
{
    __half* as = smem + (size_t)stage * STG_HALVES + AS_OFF;
    __half* bs = smem + (size_t)stage * STG_HALVES + BS_OFF;
#pragma unroll
    for (int i = 0; i < 4; ++i) {
        int c = tid + i * 256, row = c >> 3, kc = (c & 7) << 3;
        cp16(as + row * PADH + kc, Ag + (size_t)row * IN_K + kbase + kc);
    }
#pragma unroll
    for (int i = 0; i < 4; ++i) {
        int c = tid + i * 256, row = c >> 3, kc = (c & 7) << 3;
        cp16(bs + row * PADH + kc, Bg + (size_t)row * IN_K + kbase + kc);
    }
    cp_commit();
}

__global__ __launch_bounds__(256, 2) void gemm_kernel(const float* __restrict__ bias,
                                                      float* __restrict__ Y)
{
    extern __shared__ __half smem[];
    const uint32_t sbase = smem_u32(smem);
    const int tid = threadIdx.x;
    const int wid = tid >> 5, lane = tid & 31;
    const int warp_m = wid & 1, warp_n = wid >> 1;   // 2 x 4 warps; warp tile 64x32
    const int gid = lane >> 2, tig = lane & 3;
    const int bm = blockIdx.y * BM;
    const int bn = blockIdx.x * BN;

    const __half* Ag = g_X + (size_t)bm * IN_K;
    const __half* Bg = g_W + (size_t)bn * IN_K;

    const int lg = lane >> 3, lr = lane & 7;
    // A x4: g0:(m+0,k+0) g1:(m+8,k+0) g2:(m+0,k+8) g3:(m+8,k+8)
    const uint32_t aLane = (uint32_t)(((warp_m * 64 + (lg & 1) * 8 + lr) * PADH
                                       + (lg >> 1) * 8) * 2);
    // B x4: g0:(n+0,k+0) g1:(n+0,k+8) g2:(n+8,k+0) g3:(n+8,k+8)
    const uint32_t bLane = (uint32_t)(((warp_n * 32 + (lg >> 1) * 8 + lr) * PADH
                                       + (lg & 1) * 8 + BS_OFF) * 2);

    float acc[4][4][4];
#pragma unroll
    for (int i = 0; i < 4; ++i)
#pragma unroll
        for (int j = 0; j < 4; ++j)
#pragma unroll
            for (int q = 0; q < 4; ++q) acc[i][j][q] = 0.f;

    issue_stage(smem, 0, 0 * BK, Ag, Bg, tid);
    issue_stage(smem, 1, 1 * BK, Ag, Bg, tid);

    for (int kt = 0; kt < NKT; ++kt) {
        // RACE FIX: on the final iteration the current group is the newest
        // committed group, so wait_group 1 would NOT wait for it. Drain fully.
        if (kt == NKT - 1) cp_wait<0>();
        else               cp_wait<1>();
        __syncthreads();

        const int ldk = kt + 2;
        if (ldk < NKT)
            issue_stage(smem, ldk % NSTG, ldk * BK, Ag, Bg, tid);

        const uint32_t stq = sbase + (uint32_t)(kt % NSTG) * STG_BYTES;
        const uint32_t aQ = stq + aLane;
        const uint32_t bQ = stq + bLane;

#pragma unroll
        for (int ks = 0; ks < 4; ++ks) {      // 4 x k16 per BK=64
            const uint32_t kOff = (uint32_t)(ks * 32);
            uint32_t a[4][4];
#pragma unroll
            for (int mt = 0; mt < 4; ++mt)
                ldsm_x4(a[mt], aQ + (uint32_t)(mt * 16 * PADH * 2) + kOff);
            uint32_t bb[2][4];
#pragma unroll
            for (int j = 0; j < 2; ++j)
                ldsm_x4(bb[j], bQ + (uint32_t)(j * 16 * PADH * 2) + kOff);
#pragma unroll
            for (int mt = 0; mt < 4; ++mt)
#pragma unroll
                for (int nt = 0; nt < 4; ++nt)
                    mma16(acc[mt][nt][0], acc[mt][nt][1], acc[mt][nt][2], acc[mt][nt][3],
                          a[mt][0], a[mt][1], a[mt][2], a[mt][3],
                          bb[nt >> 1][(nt & 1) * 2], bb[nt >> 1][(nt & 1) * 2 + 1]);
        }
    }

    // ---- epilogue: bias + store ----
#pragma unroll
    for (int mt = 0; mt < 4; ++mt) {
        const int row0 = bm + warp_m * 64 + mt * 16 + gid;
#pragma unroll
        for (int nt = 0; nt < 4; ++nt) {
            const int col = bn + warp_n * 32 + nt * 8 + tig * 2;
            const float bx = __ldg(&bias[col]);
            const float by = __ldg(&bias[col + 1]);
            float2 v0 = make_float2(acc[mt][nt][0] + bx, acc[mt][nt][1] + by);
            float2 v1 = make_float2(acc[mt][nt][2] + bx, acc[mt][nt][3] + by);
            *(float2*)&Y[(size_t)row0 * OUT_N + col] = v0;
            *(float2*)&Y[(size_t)(row0 + 8) * OUT_N + col] = v1;
        }
    }
}

// ---------------- launch ----------------------------------------------------
extern "C" void kernel_launch(void* const* d_in, const int* in_sizes, int n_in,
                              void* d_out, int out_size)
{
    const float* x       = (const float*)d_in[0];  // [4, 2048, 2048]
    const int*   indices = (const int*)  d_in[1];  // [2048, 2048]
    const float* lut     = (const float*)d_in[2];  // [16]
    const float* sA      = (const float*)d_in[3];  // [2048, 4]
    const float* sB      = (const float*)d_in[4];  // [4, 2048]
    const float* mag     = (const float*)d_in[5];  // [4]
    const float* bias    = (const float*)d_in[6];  // [2048]
    float* y = (float*)d_out;                      // [4, 2048, 2048]

    cudaFuncSetAttribute(gemm_kernel, cudaFuncAttributeMaxDynamicSharedMemorySize, DYN_SMEM);

    norm_kernel<<<8, 256>>>(sA, sB, mag);
    prep_fused_kernel<<<OUT_N + XBLOCKS, 256>>>(indices, lut, sA, sB, x);

    dim3 grid(OUT_N / BN, M_ROWS / BM);  // (16, 64)
    gemm_kernel<<<grid, 256, DYN_SMEM>>>(bias, y);
}

// round 14
// speedup vs baseline: 1.1117x; 1.0163x over previous
#include <cuda_runtime.h>
#include <cuda_fp16.h>
#include <math.h>
#include <stdint.h>

#define OUT_N  2048
#define IN_K   2048
#define M_ROWS 8192
#define RANK   4

// ---------------- scratch (static device globals; no runtime alloc) --------
__device__ float  g_coef[8];                   // [0..3]=g_r/||A_r||, [4..7]=1/||B_r||
__device__ __half g_W[(size_t)OUT_N * IN_K];   // fp16 effective weight (8 MB)
__device__ __half g_X[(size_t)M_ROWS * IN_K];  // fp16 activations (32 MB)

__device__ __forceinline__ uint32_t h2_bits(__half2 h) {
    union { __half2 h; uint32_t u; } cvt;
    cvt.h = h;
    return cvt.u;
}

// ---------------- Kernel 1: single-block coalesced norms --------------------
// 1024 threads. A: 2048 float4 rows (one per o). B: 4 rows x 512 float4.
__global__ __launch_bounds__(1024) void norm_kernel(const float* __restrict__ sA,
                                                    const float* __restrict__ sB,
                                                    const float* __restrict__ mag)
{
    __shared__ float red[32][8];
    const int tid = threadIdx.x, lid = tid & 31, wid = tid >> 5;

    float s[8] = {0.f, 0.f, 0.f, 0.f, 0.f, 0.f, 0.f, 0.f};

    // A: row o is a float4 of the 4 ranks
    const float4* A4 = (const float4*)sA;
#pragma unroll
    for (int i = 0; i < 2; ++i) {
        float4 v = A4[tid + i * 1024];
        s[0] += v.x * v.x; s[1] += v.y * v.y; s[2] += v.z * v.z; s[3] += v.w * v.w;
    }
    // B: rank r row = 512 float4
    const float4* B4 = (const float4*)sB;
#pragma unroll
    for (int r = 0; r < 4; ++r) {
        if (tid < 512) {
            float4 v = B4[r * 512 + tid];
            s[4 + r] += v.x * v.x + v.y * v.y + v.z * v.z + v.w * v.w;
        }
    }
    // warp reduce all 8
#pragma unroll
    for (int off = 16; off; off >>= 1)
#pragma unroll
        for (int q = 0; q < 8; ++q)
            s[q] += __shfl_xor_sync(0xffffffff, s[q], off);
    if (lid == 0)
#pragma unroll
        for (int q = 0; q < 8; ++q) red[wid][q] = s[q];
    __syncthreads();
    if (wid == 0) {
        float t[8];
#pragma unroll
        for (int q = 0; q < 8; ++q) t[q] = red[lid][q];
#pragma unroll
        for (int off = 16; off; off >>= 1)
#pragma unroll
            for (int q = 0; q < 8; ++q)
                t[q] += __shfl_xor_sync(0xffffffff, t[q], off);
        if (lid == 0) {
#pragma unroll
            for (int r = 0; r < 4; ++r) {
                float nrmA = fmaxf(sqrtf(t[r]), 1e-6f);
                float m = mag[r];
                float g = (m > 20.f ? m : log1pf(expf(m))) + 1e-6f;
                g_coef[r] = g / nrmA;
                g_coef[4 + r] = 1.f / fmaxf(sqrtf(t[4 + r]), 1e-6f);
            }
        }
    }
}

// ---------------- Kernel 2 (fused): build W  +  convert X -------------------
#define XBLOCKS ((M_ROWS * IN_K) / (256 * 8))   // 8192

__global__ __launch_bounds__(256) void prep_fused_kernel(const int* __restrict__ indices,
                                                         const float* __restrict__ lut,
                                                         const float* __restrict__ sA,
                                                         const float* __restrict__ sB,
                                                         const float* __restrict__ x)
{
    if (blockIdx.x >= OUT_N) {
        // ---- round_x part ----
        size_t i = ((size_t)(blockIdx.x - OUT_N) * 256 + threadIdx.x) * 8;
        float4 v0 = *(const float4*)&x[i];
        float4 v1 = *(const float4*)&x[i + 4];
        uint4 out;
        out.x = h2_bits(__floats2half2_rn(v0.x, v0.y));
        out.y = h2_bits(__floats2half2_rn(v0.z, v0.w));
        out.z = h2_bits(__floats2half2_rn(v1.x, v1.y));
        out.w = h2_bits(__floats2half2_rn(v1.z, v1.w));
        *(uint4*)&g_X[i] = out;
        return;
    }

    // ---- build_w part ----
    __shared__ float lsh[16];
    __shared__ float ash[RANK];
    const int o = blockIdx.x;
    const int tid = threadIdx.x;
    if (tid < 16) lsh[tid] = lut[tid];
    if (tid < RANK) ash[tid] = fabsf(sA[o * RANK + tid]) * g_coef[tid];
    __syncthreads();

    const float k0 = ash[0] * g_coef[4], k1 = ash[1] * g_coef[5];
    const float k2 = ash[2] * g_coef[6], k3 = ash[3] * g_coef[7];

#pragma unroll
    for (int half = 0; half < 2; ++half) {
        const int i0 = tid * 4 + half * 1024;
        const int4 idx = *(const int4*)&indices[(size_t)o * IN_K + i0];
        const float4 b0 = *(const float4*)&sB[0 * IN_K + i0];
        const float4 b1 = *(const float4*)&sB[1 * IN_K + i0];
        const float4 b2 = *(const float4*)&sB[2 * IN_K + i0];
        const float4 b3 = *(const float4*)&sB[3 * IN_K + i0];

        __half2 w01 = __floats2half2_rn(
            lsh[idx.x] * (k0 * fabsf(b0.x) + k1 * fabsf(b1.x) + k2 * fabsf(b2.x) + k3 * fabsf(b3.x)),
            lsh[idx.y] * (k0 * fabsf(b0.y) + k1 * fabsf(b1.y) + k2 * fabsf(b2.y) + k3 * fabsf(b3.y)));
        __half2 w23 = __floats2half2_rn(
            lsh[idx.z] * (k0 * fabsf(b0.z) + k1 * fabsf(b1.z) + k2 * fabsf(b2.z) + k3 * fabsf(b3.z)),
            lsh[idx.w] * (k0 * fabsf(b0.w) + k1 * fabsf(b1.w) + k2 * fabsf(b2.w) + k3 * fabsf(b3.w)));
        uint2 packed = make_uint2(h2_bits(w01), h2_bits(w23));
        *(uint2*)&g_W[(size_t)o * IN_K + i0] = packed;
    }
}

// ---------------- Kernel 3: fp16 mma.sync GEMM (R8 config, race-fixed) ------
// CTA 128x128, 256 threads (8 warps of 64x32), BK=64, 3 stages, 2 CTAs/SM.
#define BM 128
#define BN 128
#define BK 64
#define PADH 72                        // halves per smem row (64 + 8 pad = 144B)
#define STG_HALVES ((BM + BN) * PADH)
#define STG_BYTES (STG_HALVES * 2)     // 36,864 B
#define AS_OFF 0
#define BS_OFF (BM * PADH)
#define NKT (IN_K / BK)                // 32
#define NSTG 3
#define DYN_SMEM (NSTG * STG_BYTES)    // 110,592 B

__device__ __forceinline__ uint32_t smem_u32(const void* p) {
    uint32_t a;
    asm("{ .reg .u64 t; cvta.to.shared.u64 t, %1; cvt.u32.u64 %0, t; }" : "=r"(a) : "l"(p));
    return a;
}
__device__ __forceinline__ void cp16(void* dst, const void* src) {
    uint32_t d;
    asm("{ .reg .u64 t; cvta.to.shared.u64 t, %1; cvt.u32.u64 %0, t; }" : "=r"(d) : "l"(dst));
    asm volatile("cp.async.cg.shared.global [%0], [%1], 16;" :: "r"(d), "l"(src));
}
__device__ __forceinline__ void cp_commit() {
    asm volatile("cp.async.commit_group;" ::: "memory");
}
template<int N>
__device__ __forceinline__ void cp_wait() {
    asm volatile("cp.async.wait_group %0;" :: "n"(N) : "memory");
}
__device__ __forceinline__ void ldsm_x4(uint32_t* r, uint32_t addr) {
    asm volatile("ldmatrix.sync.aligned.m8n8.x4.shared.b16 {%0,%1,%2,%3}, [%4];"
                 : "=r"(r[0]), "=r"(r[1]), "=r"(r[2]), "=r"(r[3]) : "r"(addr));
}
__device__ __forceinline__ void mma16(float& c0, float& c1, float& c2, float& c3,
                                      uint32_t a0, uint32_t a1, uint32_t a2, uint32_t a3,
                                      uint32_t b0, uint32_t b1) {
    asm volatile(
        "mma.sync.aligned.m16n8k16.row.col.f32.f16.f16.f32 "
        "{%0,%1,%2,%3}, {%4,%5,%6,%7}, {%8,%9}, {%0,%1,%2,%3};"
        : "+f"(c0), "+f"(c1), "+f"(c2), "+f"(c3)
        : "r"(a0), "r"(a1), "r"(a2), "r"(a3), "r"(b0), "r"(b1));
}

__device__ __forceinline__ void issue_stage(__half* smem, int stage, int kbase,
                                            const __half* Ag, const __half* Bg, int tid)
{
    __half* as = smem + (size_t)stage * STG_HALVES + AS_OFF;
    __half* bs = smem + (size_t)stage * STG_HALVES + BS_OFF;
#pragma unroll
    for (int i = 0; i < 4; ++i) {
        int c = tid + i * 256, row = c >> 3, kc = (c & 7) << 3;
        cp16(as + row * PADH + kc, Ag + (size_t)row * IN_K + kbase + kc);
    }
#pragma unroll
    for (int i = 0; i < 4; ++i) {
        int c = tid + i * 256, row = c >> 3, kc = (c & 7) << 3;
        cp16(bs + row * PADH + kc, Bg + (size_t)row * IN_K + kbase + kc);
    }
    cp_commit();
}

struct Frags { uint32_t a[4][4]; uint32_t bb[2][4]; };

__device__ __forceinline__ void compute_iter(uint32_t aQ, uint32_t bQ,
                                             float (*acc)[4][4])
{
#pragma unroll
    for (int ks = 0; ks < 4; ++ks) {      // 4 x k16 per BK=64
        const uint32_t kOff = (uint32_t)(ks * 32);
        uint32_t a[4][4];
#pragma unroll
        for (int mt = 0; mt < 4; ++mt)
            ldsm_x4(a[mt], aQ + (uint32_t)(mt * 16 * PADH * 2) + kOff);
        uint32_t bb[2][4];
#pragma unroll
        for (int j = 0; j < 2; ++j)
            ldsm_x4(bb[j], bQ + (uint32_t)(j * 16 * PADH * 2) + kOff);
#pragma unroll
        for (int mt = 0; mt < 4; ++mt)
#pragma unroll
            for (int nt = 0; nt < 4; ++nt)
                mma16(acc[mt][nt][0], acc[mt][nt][1], acc[mt][nt][2], acc[mt][nt][3],
                      a[mt][0], a[mt][1], a[mt][2], a[mt][3],
                      bb[nt >> 1][(nt & 1) * 2], bb[nt >> 1][(nt & 1) * 2 + 1]);
    }
}

__global__ __launch_bounds__(256, 2) void gemm_kernel(const float* __restrict__ bias,
                                                      float* __restrict__ Y)
{
    extern __shared__ __half smem[];
    const uint32_t sbase = smem_u32(smem);
    const int tid = threadIdx.x;
    const int wid = tid >> 5, lane = tid & 31;
    const int warp_m = wid & 1, warp_n = wid >> 1;   // 2 x 4 warps; warp tile 64x32
    const int gid = lane >> 2, tig = lane & 3;
    const int bm = blockIdx.y * BM;
    const int bn = blockIdx.x * BN;

    const __half* Ag = g_X + (size_t)bm * IN_K;
    const __half* Bg = g_W + (size_t)bn * IN_K;

    const int lg = lane >> 3, lr = lane & 7;
    const uint32_t aLane = (uint32_t)(((warp_m * 64 + (lg & 1) * 8 + lr) * PADH
                                       + (lg >> 1) * 8) * 2);
    const uint32_t bLane = (uint32_t)(((warp_n * 32 + (lg >> 1) * 8 + lr) * PADH
                                       + (lg & 1) * 8 + BS_OFF) * 2);

    float acc[4][4][4];
#pragma unroll
    for (int i = 0; i < 4; ++i)
#pragma unroll
        for (int j = 0; j < 4; ++j)
#pragma unroll
            for (int q = 0; q < 4; ++q) acc[i][j][q] = 0.f;

    issue_stage(smem, 0, 0 * BK, Ag, Bg, tid);
    issue_stage(smem, 1, 1 * BK, Ag, Bg, tid);

    // main loop: kt = 0 .. NKT-2 (branch-free), last iteration peeled
    for (int kt = 0; kt < NKT - 1; ++kt) {
        cp_wait<1>();
        __syncthreads();

        const int ldk = kt + 2;
        if (ldk < NKT)
            issue_stage(smem, ldk % NSTG, ldk * BK, Ag, Bg, tid);

        const uint32_t stq = sbase + (uint32_t)(kt % NSTG) * STG_BYTES;
        compute_iter(stq + aLane, stq + bLane, acc);
    }
    // peeled final iteration: fully drain (the newest group IS this buffer)
    {
        cp_wait<0>();
        __syncthreads();
        const uint32_t stq = sbase + (uint32_t)((NKT - 1) % NSTG) * STG_BYTES;
        compute_iter(stq + aLane, stq + bLane, acc);
    }

    // ---- epilogue: bias + store ----
#pragma unroll
    for (int mt = 0; mt < 4; ++mt) {
        const int row0 = bm + warp_m * 64 + mt * 16 + gid;
#pragma unroll
        for (int nt = 0; nt < 4; ++nt) {
            const int col = bn + warp_n * 32 + nt * 8 + tig * 2;
            const float bx = __ldg(&bias[col]);
            const float by = __ldg(&bias[col + 1]);
            float2 v0 = make_float2(acc[mt][nt][0] + bx, acc[mt][nt][1] + by);
            float2 v1 = make_float2(acc[mt][nt][2] + bx, acc[mt][nt][3] + by);
            *(float2*)&Y[(size_t)row0 * OUT_N + col] = v0;
            *(float2*)&Y[(size_t)(row0 + 8) * OUT_N + col] = v1;
        }
    }
}

// ---------------- launch ----------------------------------------------------
extern "C" void kernel_launch(void* const* d_in, const int* in_sizes, int n_in,
                              void* d_out, int out_size)
{
    const float* x       = (const float*)d_in[0];  // [4, 2048, 2048]
    const int*   indices = (const int*)  d_in[1];  // [2048, 2048]
    const float* lut     = (const float*)d_in[2];  // [16]
    const float* sA      = (const float*)d_in[3];  // [2048, 4]
    const float* sB      = (const float*)d_in[4];  // [4, 2048]
    const float* mag     = (const float*)d_in[5];  // [4]
    const float* bias    = (const float*)d_in[6];  // [2048]
    float* y = (float*)d_out;                      // [4, 2048, 2048]

    cudaFuncSetAttribute(gemm_kernel, cudaFuncAttributeMaxDynamicSharedMemorySize, DYN_SMEM);

    norm_kernel<<<1, 1024>>>(sA, sB, mag);
    prep_fused_kernel<<<OUT_N + XBLOCKS, 256>>>(indices, lut, sA, sB, x);

    dim3 grid(OUT_N / BN, M_ROWS / BM);  // (16, 64)
    gemm_kernel<<<grid, 256, DYN_SMEM>>>(bias, y);
}

// round 15
// speedup vs baseline: 1.1139x; 1.0019x over previous
#include <cuda_runtime.h>
#include <cuda_fp16.h>
#include <math.h>
#include <stdint.h>

#define OUT_N  2048
#define IN_K   2048
#define M_ROWS 8192
#define RANK   4

// ---------------- scratch (static device globals; no runtime alloc) --------
__device__ float  g_coef[8];                   // [0..3]=g_r/||A_r||, [4..7]=1/||B_r||
__device__ int    g_flag = 0;                  // release flag for g_coef
__device__ __half g_W[(size_t)OUT_N * IN_K];   // fp16 effective weight (8 MB)
__device__ __half g_X[(size_t)M_ROWS * IN_K];  // fp16 activations (32 MB)

__device__ __forceinline__ uint32_t h2_bits(__half2 h) {
    union { __half2 h; uint32_t u; } cvt;
    cvt.h = h;
    return cvt.u;
}

// ---------------- Fused prep: norms (block 0) + convert X + build W ---------
// block 0                      : rank norms + softplus -> g_coef, release flag
// blocks [1, 1+XBLOCKS)        : X fp32->fp16, 256 thr x 8 elems
// blocks [1+XBLOCKS, +OUT_N)   : W row build (spins on flag; ~free, scheduled last)
#define XBLOCKS ((M_ROWS * IN_K) / (256 * 8))   // 8192
#define PREP_GRID (1 + XBLOCKS + OUT_N)

__global__ __launch_bounds__(256) void prep_fused_kernel(const int* __restrict__ indices,
                                                         const float* __restrict__ lut,
                                                         const float* __restrict__ sA,
                                                         const float* __restrict__ sB,
                                                         const float* __restrict__ mag,
                                                         const float* __restrict__ x)
{
    const int tid = threadIdx.x;

    if (blockIdx.x == 0) {
        // ---- norms: 256 threads, coalesced float4 ----
        __shared__ float red[8][8];
        const int lid = tid & 31, wid = tid >> 5;
        float s[8] = {0.f, 0.f, 0.f, 0.f, 0.f, 0.f, 0.f, 0.f};
        const float4* A4 = (const float4*)sA;   // 2048 float4 rows (one per o)
#pragma unroll
        for (int i = 0; i < 8; ++i) {
            float4 v = A4[tid + i * 256];
            s[0] += v.x * v.x; s[1] += v.y * v.y; s[2] += v.z * v.z; s[3] += v.w * v.w;
        }
        const float4* B4 = (const float4*)sB;   // 4 rows x 512 float4
#pragma unroll
        for (int r = 0; r < 4; ++r)
#pragma unroll
            for (int j = 0; j < 2; ++j) {
                float4 v = B4[r * 512 + tid + j * 256];
                s[4 + r] += v.x * v.x + v.y * v.y + v.z * v.z + v.w * v.w;
            }
#pragma unroll
        for (int off = 16; off; off >>= 1)
#pragma unroll
            for (int q = 0; q < 8; ++q)
                s[q] += __shfl_xor_sync(0xffffffff, s[q], off);
        if (lid == 0)
#pragma unroll
            for (int q = 0; q < 8; ++q) red[wid][q] = s[q];
        __syncthreads();
        if (tid == 0) {
            float t[8];
#pragma unroll
            for (int q = 0; q < 8; ++q) {
                t[q] = red[0][q];
                for (int w = 1; w < 8; ++w) t[q] += red[w][q];
            }
#pragma unroll
            for (int r = 0; r < 4; ++r) {
                float nrmA = fmaxf(sqrtf(t[r]), 1e-6f);
                float m = mag[r];
                float g = (m > 20.f ? m : log1pf(expf(m))) + 1e-6f;
                g_coef[r] = g / nrmA;
                g_coef[4 + r] = 1.f / fmaxf(sqrtf(t[4 + r]), 1e-6f);
            }
            __threadfence();
            atomicExch(&g_flag, 1);
        }
        return;
    }

    if (blockIdx.x < 1 + XBLOCKS) {
        // ---- round_x: no dependency on norms ----
        size_t i = ((size_t)(blockIdx.x - 1) * 256 + tid) * 8;
        float4 v0 = *(const float4*)&x[i];
        float4 v1 = *(const float4*)&x[i + 4];
        uint4 out;
        out.x = h2_bits(__floats2half2_rn(v0.x, v0.y));
        out.y = h2_bits(__floats2half2_rn(v0.z, v0.w));
        out.z = h2_bits(__floats2half2_rn(v1.x, v1.y));
        out.w = h2_bits(__floats2half2_rn(v1.z, v1.w));
        *(uint4*)&g_X[i] = out;
        return;
    }

    // ---- build_w: gated on g_coef (block 0 always finishes first in practice;
    //      spin is provably deadlock-free since block 0 depends on nothing) ----
    __shared__ float lsh[16];
    __shared__ float ash[RANK];
    const int o = blockIdx.x - 1 - XBLOCKS;

    if (tid == 0) {
        while (atomicAdd(&g_flag, 0) == 0) { }
    }
    __syncthreads();
    __threadfence();   // acquire: order g_coef reads after flag observation

    if (tid < 16) lsh[tid] = lut[tid];
    if (tid < RANK) ash[tid] = fabsf(sA[o * RANK + tid]) * g_coef[tid];
    __syncthreads();

    const float k0 = ash[0] * g_coef[4], k1 = ash[1] * g_coef[5];
    const float k2 = ash[2] * g_coef[6], k3 = ash[3] * g_coef[7];

#pragma unroll
    for (int half = 0; half < 2; ++half) {
        const int i0 = tid * 4 + half * 1024;
        const int4 idx = *(const int4*)&indices[(size_t)o * IN_K + i0];
        const float4 b0 = *(const float4*)&sB[0 * IN_K + i0];
        const float4 b1 = *(const float4*)&sB[1 * IN_K + i0];
        const float4 b2 = *(const float4*)&sB[2 * IN_K + i0];
        const float4 b3 = *(const float4*)&sB[3 * IN_K + i0];

        __half2 w01 = __floats2half2_rn(
            lsh[idx.x] * (k0 * fabsf(b0.x) + k1 * fabsf(b1.x) + k2 * fabsf(b2.x) + k3 * fabsf(b3.x)),
            lsh[idx.y] * (k0 * fabsf(b0.y) + k1 * fabsf(b1.y) + k2 * fabsf(b2.y) + k3 * fabsf(b3.y)));
        __half2 w23 = __floats2half2_rn(
            lsh[idx.z] * (k0 * fabsf(b0.z) + k1 * fabsf(b1.z) + k2 * fabsf(b2.z) + k3 * fabsf(b3.z)),
            lsh[idx.w] * (k0 * fabsf(b0.w) + k1 * fabsf(b1.w) + k2 * fabsf(b2.w) + k3 * fabsf(b3.w)));
        uint2 packed = make_uint2(h2_bits(w01), h2_bits(w23));
        *(uint2*)&g_W[(size_t)o * IN_K + i0] = packed;
    }
}

// ---------------- GEMM: fp16 mma.sync (R8 config, race-fixed) ---------------
// CTA 128x128, 256 threads (8 warps of 64x32), BK=64, 3 stages, 2 CTAs/SM.
#define BM 128
#define BN 128
#define BK 64
#define PADH 72                        // halves per smem row (64 + 8 pad = 144B)
#define STG_HALVES ((BM + BN) * PADH)
#define STG_BYTES (STG_HALVES * 2)     // 36,864 B
#define AS_OFF 0
#define BS_OFF (BM * PADH)
#define NKT (IN_K / BK)                // 32
#define NSTG 3
#define DYN_SMEM (NSTG * STG_BYTES)    // 110,592 B

__device__ __forceinline__ uint32_t smem_u32(const void* p) {
    uint32_t a;
    asm("{ .reg .u64 t; cvta.to.shared.u64 t, %1; cvt.u32.u64 %0, t; }" : "=r"(a) : "l"(p));
    return a;
}
__device__ __forceinline__ void cp16(void* dst, const void* src) {
    uint32_t d;
    asm("{ .reg .u64 t; cvta.to.shared.u64 t, %1; cvt.u32.u64 %0, t; }" : "=r"(d) : "l"(dst));
    asm volatile("cp.async.cg.shared.global [%0], [%1], 16;" :: "r"(d), "l"(src));
}
__device__ __forceinline__ void cp_commit() {
    asm volatile("cp.async.commit_group;" ::: "memory");
}
template<int N>
__device__ __forceinline__ void cp_wait() {
    asm volatile("cp.async.wait_group %0;" :: "n"(N) : "memory");
}
__device__ __forceinline__ void ldsm_x4(uint32_t* r, uint32_t addr) {
    asm volatile("ldmatrix.sync.aligned.m8n8.x4.shared.b16 {%0,%1,%2,%3}, [%4];"
                 : "=r"(r[0]), "=r"(r[1]), "=r"(r[2]), "=r"(r[3]) : "r"(addr));
}
__device__ __forceinline__ void mma16(float& c0, float& c1, float& c2, float& c3,
                                      uint32_t a0, uint32_t a1, uint32_t a2, uint32_t a3,
                                      uint32_t b0, uint32_t b1) {
    asm volatile(
        "mma.sync.aligned.m16n8k16.row.col.f32.f16.f16.f32 "
        "{%0,%1,%2,%3}, {%4,%5,%6,%7}, {%8,%9}, {%0,%1,%2,%3};"
        : "+f"(c0), "+f"(c1), "+f"(c2), "+f"(c3)
        : "r"(a0), "r"(a1), "r"(a2), "r"(a3), "r"(b0), "r"(b1));
}

__device__ __forceinline__ void issue_stage(__half* smem, int stage, int kbase,
                                            const __half* Ag, const __half* Bg, int tid)
{
    __half* as = smem + (size_t)stage * STG_HALVES + AS_OFF;
    __half* bs = smem + (size_t)stage * STG_HALVES + BS_OFF;
#pragma unroll
    for (int i = 0; i < 4; ++i) {
        int c = tid + i * 256, row = c >> 3, kc = (c & 7) << 3;
        cp16(as + row * PADH + kc, Ag + (size_t)row * IN_K + kbase + kc);
    }
#pragma unroll
    for (int i = 0; i < 4; ++i) {
        int c = tid + i * 256, row = c >> 3, kc = (c & 7) << 3;
        cp16(bs + row * PADH + kc, Bg + (size_t)row * IN_K + kbase + kc);
    }
    cp_commit();
}

__device__ __forceinline__ void compute_iter(uint32_t aQ, uint32_t bQ,
                                             float (*acc)[4][4])
{
#pragma unroll
    for (int ks = 0; ks < 4; ++ks) {      // 4 x k16 per BK=64
        const uint32_t kOff = (uint32_t)(ks * 32);
        uint32_t a[4][4];
#pragma unroll
        for (int mt = 0; mt < 4; ++mt)
            ldsm_x4(a[mt], aQ + (uint32_t)(mt * 16 * PADH * 2) + kOff);
        uint32_t bb[2][4];
#pragma unroll
        for (int j = 0; j < 2; ++j)
            ldsm_x4(bb[j], bQ + (uint32_t)(j * 16 * PADH * 2) + kOff);
#pragma unroll
        for (int mt = 0; mt < 4; ++mt)
#pragma unroll
            for (int nt = 0; nt < 4; ++nt)
                mma16(acc[mt][nt][0], acc[mt][nt][1], acc[mt][nt][2], acc[mt][nt][3],
                      a[mt][0], a[mt][1], a[mt][2], a[mt][3],
                      bb[nt >> 1][(nt & 1) * 2], bb[nt >> 1][(nt & 1) * 2 + 1]);
    }
}

__global__ __launch_bounds__(256, 2) void gemm_kernel(const float* __restrict__ bias,
                                                      float* __restrict__ Y)
{
    extern __shared__ __half smem[];
    const uint32_t sbase = smem_u32(smem);
    const int tid = threadIdx.x;
    const int wid = tid >> 5, lane = tid & 31;
    const int warp_m = wid & 1, warp_n = wid >> 1;   // 2 x 4 warps; warp tile 64x32
    const int gid = lane >> 2, tig = lane & 3;
    const int bm = blockIdx.y * BM;
    const int bn = blockIdx.x * BN;

    const __half* Ag = g_X + (size_t)bm * IN_K;
    const __half* Bg = g_W + (size_t)bn * IN_K;

    const int lg = lane >> 3, lr = lane & 7;
    const uint32_t aLane = (uint32_t)(((warp_m * 64 + (lg & 1) * 8 + lr) * PADH
                                       + (lg >> 1) * 8) * 2);
    const uint32_t bLane = (uint32_t)(((warp_n * 32 + (lg >> 1) * 8 + lr) * PADH
                                       + (lg & 1) * 8 + BS_OFF) * 2);

    float acc[4][4][4];
#pragma unroll
    for (int i = 0; i < 4; ++i)
#pragma unroll
        for (int j = 0; j < 4; ++j)
#pragma unroll
            for (int q = 0; q < 4; ++q) acc[i][j][q] = 0.f;

    issue_stage(smem, 0, 0 * BK, Ag, Bg, tid);
    issue_stage(smem, 1, 1 * BK, Ag, Bg, tid);

    for (int kt = 0; kt < NKT - 1; ++kt) {
        cp_wait<1>();
        __syncthreads();

        const int ldk = kt + 2;
        if (ldk < NKT)
            issue_stage(smem, ldk % NSTG, ldk * BK, Ag, Bg, tid);

        const uint32_t stq = sbase + (uint32_t)(kt % NSTG) * STG_BYTES;
        compute_iter(stq + aLane, stq + bLane, acc);
    }
    {   // peeled final iteration: full drain (newest group IS this buffer)
        cp_wait<0>();
        __syncthreads();
        const uint32_t stq = sbase + (uint32_t)((NKT - 1) % NSTG) * STG_BYTES;
        compute_iter(stq + aLane, stq + bLane, acc);
    }

    // ---- epilogue: bias + store ----
#pragma unroll
    for (int mt = 0; mt < 4; ++mt) {
        const int row0 = bm + warp_m * 64 + mt * 16 + gid;
#pragma unroll
        for (int nt = 0; nt < 4; ++nt) {
            const int col = bn + warp_n * 32 + nt * 8 + tig * 2;
            const float bx = __ldg(&bias[col]);
            const float by = __ldg(&bias[col + 1]);
            float2 v0 = make_float2(acc[mt][nt][0] + bx, acc[mt][nt][1] + by);
            float2 v1 = make_float2(acc[mt][nt][2] + bx, acc[mt][nt][3] + by);
            *(float2*)&Y[(size_t)row0 * OUT_N + col] = v0;
            *(float2*)&Y[(size_t)(row0 + 8) * OUT_N + col] = v1;
        }
    }
}

// ---------------- launch ----------------------------------------------------
extern "C" void kernel_launch(void* const* d_in, const int* in_sizes, int n_in,
                              void* d_out, int out_size)
{
    const float* x       = (const float*)d_in[0];  // [4, 2048, 2048]
    const int*   indices = (const int*)  d_in[1];  // [2048, 2048]
    const float* lut     = (const float*)d_in[2];  // [16]
    const float* sA      = (const float*)d_in[3];  // [2048, 4]
    const float* sB      = (const float*)d_in[4];  // [4, 2048]
    const float* mag     = (const float*)d_in[5];  // [4]
    const float* bias    = (const float*)d_in[6];  // [2048]
    float* y = (float*)d_out;                      // [4, 2048, 2048]

    cudaFuncSetAttribute(gemm_kernel, cudaFuncAttributeMaxDynamicSharedMemorySize, DYN_SMEM);

    prep_fused_kernel<<<PREP_GRID, 256>>>(indices, lut, sA, sB, mag, x);

    dim3 grid(OUT_N / BN, M_ROWS / BM);  // (16, 64)
    gemm_kernel<<<grid, 256, DYN_SMEM>>>(bias, y);
}